// round 4
// baseline (speedup 1.0000x reference)
#include <cuda_runtime.h>
#include <stdint.h>

#define NMAX 100000
#define EMAX 1600000
#define F    64
#define F4   16          // float4 per node row
#define SCAN_B 1024
#define NB1MAX ((NMAX + SCAN_B - 1) / SCAN_B)   // 98

// ---- scratch (device globals: allocation-free) ----
__device__ int    g_degi[NMAX];            // in-degree counts (no self loop)
__device__ float  g_dinv[NMAX];
__device__ int    g_src [EMAX];
__device__ int    g_dst [EMAX];
__device__ int    g_off [NMAX + 1];        // CSR offsets
__device__ int    g_cur [NMAX];            // placement cursors
__device__ int    g_bsum[NB1MAX + 1];      // scan block sums
__device__ float2 g_er  [EMAX];            // edge records: {src(bits), norm}
__device__ float4 g_h   [(size_t)NMAX * F4];
__device__ float4 g_agg [(size_t)NMAX * F4];

// ---------------------------------------------------------------------------
__global__ void k_zero_deg(int n) {
    int i = blockIdx.x * blockDim.x + threadIdx.x;
    if (i < n) g_degi[i] = 0;
}

// edge_index is int32 (JAX x64-disabled downcasts the reference's int64).
// Count in-degree with int atomics; stash narrow copies.
__global__ void k_count(const int* __restrict__ ei, int E) {
    int e = blockIdx.x * blockDim.x + threadIdx.x;
    if (e < E) {
        int s = ei[e];
        int d = ei[e + E];
        g_src[e] = s;
        g_dst[e] = d;
        atomicAdd(&g_degi[d], 1);
    }
}

__global__ void k_dinv(int n) {
    int i = blockIdx.x * blockDim.x + threadIdx.x;
    if (i < n) g_dinv[i] = rsqrtf((float)g_degi[i] + 1.0f);  // + self loop
}

// ---- exclusive scan over degrees (3 stages) ----
__global__ void k_scan_local(int n) {
    __shared__ int wsum[32];
    int i = blockIdx.x * SCAN_B + threadIdx.x;
    int lane = threadIdx.x & 31, wid = threadIdx.x >> 5;
    int v = (i < n) ? g_degi[i] : 0;
    int s = v;
#pragma unroll
    for (int o = 1; o < 32; o <<= 1) {
        int u = __shfl_up_sync(0xffffffffu, s, o);
        if (lane >= o) s += u;
    }
    if (lane == 31) wsum[wid] = s;
    __syncthreads();
    if (wid == 0) {
        int ws = wsum[lane];
#pragma unroll
        for (int o = 1; o < 32; o <<= 1) {
            int u = __shfl_up_sync(0xffffffffu, ws, o);
            if (lane >= o) ws += u;
        }
        wsum[lane] = ws;
    }
    __syncthreads();
    int excl = s - v + (wid > 0 ? wsum[wid - 1] : 0);
    if (i < n) g_off[i] = excl;
    if (threadIdx.x == 0) g_bsum[blockIdx.x] = wsum[31];
}

__global__ void k_scan_bsums(int nb) {   // single block, 128 threads (nb <= 98)
    __shared__ int wsum[4];
    int t = threadIdx.x;
    int lane = t & 31, wid = t >> 5;
    int v = (t < nb) ? g_bsum[t] : 0;
    int s = v;
#pragma unroll
    for (int o = 1; o < 32; o <<= 1) {
        int u = __shfl_up_sync(0xffffffffu, s, o);
        if (lane >= o) s += u;
    }
    if (lane == 31) wsum[wid] = s;
    __syncthreads();
    int base = 0;
    for (int w = 0; w < wid; w++) base += wsum[w];
    if (t < nb) g_bsum[t] = s - v + base;    // exclusive
}

__global__ void k_scan_add(int n, int E) {
    int i = blockIdx.x * SCAN_B + threadIdx.x;
    if (i < n) {
        int o = g_off[i] + g_bsum[blockIdx.x];
        g_off[i] = o;
        g_cur[i] = o;
    }
    if (i == 0) g_off[n] = E;
}

// Place edge records into dst buckets.
__global__ void k_place(int E) {
    int e = blockIdx.x * blockDim.x + threadIdx.x;
    if (e < E) {
        int s = g_src[e];
        int d = g_dst[e];
        int pos = atomicAdd(&g_cur[d], 1);
        float nv = g_dinv[s] * g_dinv[d];
        g_er[pos] = make_float2(__int_as_float(s), nv);
    }
}

// ---------------------------------------------------------------------------
// GEMM: h = in @ W (K=64). 16 rows/block, 256 threads, 1x4 out per thread.
// Epilogue seeds g_agg with self-loop term h*dinv^2.
template <bool RELU_BIAS>
__global__ void k_gemm(const float* in, const float* __restrict__ W,
                       const float* __restrict__ bias, int n)
{
    __shared__ float Ws[F * F];
    __shared__ float xs[16 * F];

    int tid = threadIdx.x;
    int tx = tid & 15;
    int ty = tid >> 4;
    int r0 = blockIdx.x * 16;

    for (int i = tid; i < F * F; i += 256) Ws[i] = W[i];

    for (int i = tid; i < 16 * F; i += 256) {
        int row = i >> 6;
        int k   = i & 63;
        int gr  = r0 + row;
        float v;
        if (RELU_BIAS) {
            v = (gr < n) ? reinterpret_cast<const float*>(g_agg)[(size_t)gr * F + k] : 0.0f;
            v = fmaxf(v + __ldg(&bias[k]), 0.0f);
        } else {
            v = (gr < n) ? in[(size_t)gr * F + k] : 0.0f;
        }
        xs[i] = v;
    }
    __syncthreads();

    float4 acc = make_float4(0.f, 0.f, 0.f, 0.f);
#pragma unroll
    for (int k = 0; k < F; k++) {
        float  xv = xs[ty * F + k];
        float4 w  = *reinterpret_cast<const float4*>(&Ws[k * F + tx * 4]);
        acc.x = fmaf(xv, w.x, acc.x);
        acc.y = fmaf(xv, w.y, acc.y);
        acc.z = fmaf(xv, w.z, acc.z);
        acc.w = fmaf(xv, w.w, acc.w);
    }

    int row = r0 + ty;
    if (row < n) {
        size_t idx = (size_t)row * F4 + tx;
        g_h[idx] = acc;
        float di = g_dinv[row];
        float sc = di * di;
        g_agg[idx] = make_float4(acc.x * sc, acc.y * sc, acc.z * sc, acc.w * sc);
    }
}

// ---------------------------------------------------------------------------
// Aggregate: 16 lanes per node; lane owns one float4 slice. Registers only,
// one non-atomic store per node. No float atomics anywhere.
__global__ void k_aggregate(int n) {
    int t = blockIdx.x * blockDim.x + threadIdx.x;
    int node = t >> 4;
    if (node >= n) return;
    int lane = t & 15;

    int beg = g_off[node];
    int end = g_off[node + 1];

    size_t idx = (size_t)node * F4 + lane;
    float4 acc = g_agg[idx];   // self-loop seed from GEMM epilogue

    int i = beg;
    for (; i + 2 <= end; i += 2) {
        float2 r0 = g_er[i];
        float2 r1 = g_er[i + 1];
        int   s0 = __float_as_int(r0.x);
        int   s1 = __float_as_int(r1.x);
        float4 v0 = __ldg(&g_h[(size_t)s0 * F4 + lane]);
        float4 v1 = __ldg(&g_h[(size_t)s1 * F4 + lane]);
        acc.x = fmaf(v0.x, r0.y, acc.x);
        acc.y = fmaf(v0.y, r0.y, acc.y);
        acc.z = fmaf(v0.z, r0.y, acc.z);
        acc.w = fmaf(v0.w, r0.y, acc.w);
        acc.x = fmaf(v1.x, r1.y, acc.x);
        acc.y = fmaf(v1.y, r1.y, acc.y);
        acc.z = fmaf(v1.z, r1.y, acc.z);
        acc.w = fmaf(v1.w, r1.y, acc.w);
    }
    if (i < end) {
        float2 r0 = g_er[i];
        int   s0 = __float_as_int(r0.x);
        float4 v0 = __ldg(&g_h[(size_t)s0 * F4 + lane]);
        acc.x = fmaf(v0.x, r0.y, acc.x);
        acc.y = fmaf(v0.y, r0.y, acc.y);
        acc.z = fmaf(v0.z, r0.y, acc.z);
        acc.w = fmaf(v0.w, r0.y, acc.w);
    }
    g_agg[idx] = acc;
}

// ---------------------------------------------------------------------------
__global__ void k_out(const float* __restrict__ b, float* __restrict__ out, int n) {
    int t = blockIdx.x * blockDim.x + threadIdx.x;
    if (t >= n * F4) return;
    int lane = t & 15;
    float b0 = __ldg(&b[lane * 4 + 0]);
    float b1 = __ldg(&b[lane * 4 + 1]);
    float b2 = __ldg(&b[lane * 4 + 2]);
    float b3 = __ldg(&b[lane * 4 + 3]);
    float4 a = g_agg[t];
    float4 o;
    o.x = fmaxf(a.x + b0, 0.f);
    o.y = fmaxf(a.y + b1, 0.f);
    o.z = fmaxf(a.z + b2, 0.f);
    o.w = fmaxf(a.w + b3, 0.f);
    reinterpret_cast<float4*>(out)[t] = o;
}

// ---------------------------------------------------------------------------
extern "C" void kernel_launch(void* const* d_in, const int* in_sizes, int n_in,
                              void* d_out, int out_size)
{
    const float* x  = (const float*)d_in[0];
    const int*   ei = (const int*)d_in[1];     // int32 (JAX default x64-off)
    const float* W1 = (const float*)d_in[2];
    const float* b1 = (const float*)d_in[3];
    const float* W2 = (const float*)d_in[4];
    const float* b2 = (const float*)d_in[5];
    float*       out = (float*)d_out;

    int n = in_sizes[0] / F;       // 100000
    int E = in_sizes[1] / 2;       // 1600000
    if (n > NMAX) n = NMAX;
    if (E > EMAX) E = EMAX;

    int nb  = (n + 255) / 256;
    int eb  = (E + 255) / 256;
    int gb  = (n + 15) / 16;
    int ab  = (n * 16 + 255) / 256;
    int ob  = (n * F4 + 255) / 256;
    int nb1 = (n + SCAN_B - 1) / SCAN_B;

    // ---- CSR build (int atomics only) ----
    k_zero_deg  <<<nb, 256>>>(n);
    k_count     <<<eb, 256>>>(ei, E);
    k_dinv      <<<nb, 256>>>(n);
    k_scan_local<<<nb1, SCAN_B>>>(n);
    k_scan_bsums<<<1, 128>>>(nb1);
    k_scan_add  <<<nb1, SCAN_B>>>(n, E);
    k_place     <<<eb, 256>>>(E);

    // ---- layer 1 ----
    k_gemm<false><<<gb, 256>>>(x, W1, b1, n);
    k_aggregate  <<<ab, 256>>>(n);

    // ---- layer 2 (bias+relu of layer 1 fused into GEMM input load) ----
    k_gemm<true> <<<gb, 256>>>(x /*unused*/, W2, b1, n);
    k_aggregate  <<<ab, 256>>>(n);

    // ---- epilogue ----
    k_out        <<<ob, 256>>>(b2, out, n);
}

// round 5
// speedup vs baseline: 1.0701x; 1.0701x over previous
#include <cuda_runtime.h>
#include <stdint.h>

#define NMAX 100000
#define EMAX 1600000
#define F    64
#define F4   16          // float4 per node row
#define SCAN_B 1024
#define NB1MAX ((NMAX + SCAN_B - 1) / SCAN_B)   // 98

// ---- scratch (device globals: allocation-free) ----
__device__ int    g_degi[NMAX];            // in-degree counts (no self loop)
__device__ float  g_dinv[NMAX];
__device__ int    g_off [NMAX + 1];        // CSR offsets
__device__ int    g_cur [NMAX];            // placement cursors
__device__ int    g_bsum[NB1MAX + 1];      // scan block sums
__device__ int    g_es  [EMAX];            // edge records: src only (h is pre-scaled)
__device__ float4 g_h   [(size_t)NMAX * F4];   // h*dinv (pre-scaled)
__device__ float4 g_agg [(size_t)NMAX * F4];   // layer-1 aggregate (pre bias/relu)

// ---------------------------------------------------------------------------
__global__ void k_zero_deg(int n) {
    int i = blockIdx.x * blockDim.x + threadIdx.x;
    if (i < n) g_degi[i] = 0;
}

// Count in-degree (int atomics). Only the dst half of edge_index is needed.
__global__ void k_count(const int* __restrict__ ei, int E) {
    int e = blockIdx.x * blockDim.x + threadIdx.x;
    if (e < E) atomicAdd(&g_degi[ei[e + E]], 1);
}

__global__ void k_dinv(int n) {
    int i = blockIdx.x * blockDim.x + threadIdx.x;
    if (i < n) g_dinv[i] = rsqrtf((float)g_degi[i] + 1.0f);  // + self loop
}

// ---- exclusive scan over degrees (3 stages) ----
__global__ void k_scan_local(int n) {
    __shared__ int wsum[32];
    int i = blockIdx.x * SCAN_B + threadIdx.x;
    int lane = threadIdx.x & 31, wid = threadIdx.x >> 5;
    int v = (i < n) ? g_degi[i] : 0;
    int s = v;
#pragma unroll
    for (int o = 1; o < 32; o <<= 1) {
        int u = __shfl_up_sync(0xffffffffu, s, o);
        if (lane >= o) s += u;
    }
    if (lane == 31) wsum[wid] = s;
    __syncthreads();
    if (wid == 0) {
        int ws = wsum[lane];
#pragma unroll
        for (int o = 1; o < 32; o <<= 1) {
            int u = __shfl_up_sync(0xffffffffu, ws, o);
            if (lane >= o) ws += u;
        }
        wsum[lane] = ws;
    }
    __syncthreads();
    int excl = s - v + (wid > 0 ? wsum[wid - 1] : 0);
    if (i < n) g_off[i] = excl;
    if (threadIdx.x == 0) g_bsum[blockIdx.x] = wsum[31];
}

__global__ void k_scan_bsums(int nb) {   // single block, 128 threads (nb <= 98)
    __shared__ int wsum[4];
    int t = threadIdx.x;
    int lane = t & 31, wid = t >> 5;
    int v = (t < nb) ? g_bsum[t] : 0;
    int s = v;
#pragma unroll
    for (int o = 1; o < 32; o <<= 1) {
        int u = __shfl_up_sync(0xffffffffu, s, o);
        if (lane >= o) s += u;
    }
    if (lane == 31) wsum[wid] = s;
    __syncthreads();
    int base = 0;
    for (int w = 0; w < wid; w++) base += wsum[w];
    if (t < nb) g_bsum[t] = s - v + base;    // exclusive
}

__global__ void k_scan_add(int n, int E) {
    int i = blockIdx.x * SCAN_B + threadIdx.x;
    if (i < n) {
        int o = g_off[i] + g_bsum[blockIdx.x];
        g_off[i] = o;
        g_cur[i] = o;
    }
    if (i == 0) g_off[n] = E;
}

// Place src into dst bucket (reads edge_index straight from L2).
__global__ void k_place(const int* __restrict__ ei, int E) {
    int e = blockIdx.x * blockDim.x + threadIdx.x;
    if (e < E) {
        int s = ei[e];
        int d = ei[e + E];
        int pos = atomicAdd(&g_cur[d], 1);
        g_es[pos] = s;
    }
}

// ---------------------------------------------------------------------------
// GEMM: g_h[r][:] = (in[r][:] @ W) * dinv[r]  (pre-scaled).
// 16 rows/block, 256 threads, 1x4 out per thread.
// RELU_BIAS: input transform v -> relu(v + bias[k]) (layer 2 reads layer-1 agg).
template <bool RELU_BIAS>
__global__ void k_gemm(const float* in, const float* __restrict__ W,
                       const float* __restrict__ bias, int n)
{
    __shared__ float Ws[F * F];
    __shared__ float xs[16 * F];

    int tid = threadIdx.x;
    int tx = tid & 15;
    int ty = tid >> 4;
    int r0 = blockIdx.x * 16;

    for (int i = tid; i < F * F; i += 256) Ws[i] = W[i];

    for (int i = tid; i < 16 * F; i += 256) {
        int row = i >> 6;
        int k   = i & 63;
        int gr  = r0 + row;
        float v;
        if (RELU_BIAS) {
            v = (gr < n) ? reinterpret_cast<const float*>(g_agg)[(size_t)gr * F + k] : 0.0f;
            v = fmaxf(v + __ldg(&bias[k]), 0.0f);
        } else {
            v = (gr < n) ? in[(size_t)gr * F + k] : 0.0f;
        }
        xs[i] = v;
    }
    __syncthreads();

    float4 acc = make_float4(0.f, 0.f, 0.f, 0.f);
#pragma unroll
    for (int k = 0; k < F; k++) {
        float  xv = xs[ty * F + k];
        float4 w  = *reinterpret_cast<const float4*>(&Ws[k * F + tx * 4]);
        acc.x = fmaf(xv, w.x, acc.x);
        acc.y = fmaf(xv, w.y, acc.y);
        acc.z = fmaf(xv, w.z, acc.z);
        acc.w = fmaf(xv, w.w, acc.w);
    }

    int row = r0 + ty;
    if (row < n) {
        float di = g_dinv[row];
        g_h[(size_t)row * F4 + tx] =
            make_float4(acc.x * di, acc.y * di, acc.z * di, acc.w * di);
    }
}

// ---------------------------------------------------------------------------
// Aggregate: 16 lanes/node, lane owns a float4 slice; register accumulation,
// one non-atomic store per node. Plain adds (h pre-scaled); final *dinv[node].
// FINAL=false: write g_agg (layer 1).  FINAL=true: write relu(.+b) to out.
template <bool FINAL>
__global__ void k_aggregate(const float* __restrict__ b, float* __restrict__ out, int n) {
    int t = blockIdx.x * blockDim.x + threadIdx.x;
    int node = t >> 4;
    if (node >= n) return;
    int lane = t & 15;

    int beg = g_off[node];
    int end = g_off[node + 1];

    size_t idx = (size_t)node * F4 + lane;
    float4 acc = g_h[idx];   // self-loop term (already *dinv[node])

    int i = beg;
    for (; i + 4 <= end; i += 4) {
        int s0 = __ldg(&g_es[i]);
        int s1 = __ldg(&g_es[i + 1]);
        int s2 = __ldg(&g_es[i + 2]);
        int s3 = __ldg(&g_es[i + 3]);
        float4 v0 = __ldg(&g_h[(size_t)s0 * F4 + lane]);
        float4 v1 = __ldg(&g_h[(size_t)s1 * F4 + lane]);
        float4 v2 = __ldg(&g_h[(size_t)s2 * F4 + lane]);
        float4 v3 = __ldg(&g_h[(size_t)s3 * F4 + lane]);
        acc.x += v0.x + v1.x + v2.x + v3.x;
        acc.y += v0.y + v1.y + v2.y + v3.y;
        acc.z += v0.z + v1.z + v2.z + v3.z;
        acc.w += v0.w + v1.w + v2.w + v3.w;
    }
    for (; i < end; i++) {
        int s0 = __ldg(&g_es[i]);
        float4 v0 = __ldg(&g_h[(size_t)s0 * F4 + lane]);
        acc.x += v0.x; acc.y += v0.y; acc.z += v0.z; acc.w += v0.w;
    }

    float di = g_dinv[node];
    if (FINAL) {
        float b0 = __ldg(&b[lane * 4 + 0]);
        float b1 = __ldg(&b[lane * 4 + 1]);
        float b2 = __ldg(&b[lane * 4 + 2]);
        float b3 = __ldg(&b[lane * 4 + 3]);
        float4 o;
        o.x = fmaxf(fmaf(acc.x, di, b0), 0.f);
        o.y = fmaxf(fmaf(acc.y, di, b1), 0.f);
        o.z = fmaxf(fmaf(acc.z, di, b2), 0.f);
        o.w = fmaxf(fmaf(acc.w, di, b3), 0.f);
        reinterpret_cast<float4*>(out)[idx] = o;
    } else {
        g_agg[idx] = make_float4(acc.x * di, acc.y * di, acc.z * di, acc.w * di);
    }
}

// ---------------------------------------------------------------------------
extern "C" void kernel_launch(void* const* d_in, const int* in_sizes, int n_in,
                              void* d_out, int out_size)
{
    const float* x  = (const float*)d_in[0];
    const int*   ei = (const int*)d_in[1];     // int32 (JAX default x64-off)
    const float* W1 = (const float*)d_in[2];
    const float* b1 = (const float*)d_in[3];
    const float* W2 = (const float*)d_in[4];
    const float* b2 = (const float*)d_in[5];
    float*       out = (float*)d_out;

    int n = in_sizes[0] / F;       // 100000
    int E = in_sizes[1] / 2;       // 1600000
    if (n > NMAX) n = NMAX;
    if (E > EMAX) E = EMAX;

    int nb  = (n + 255) / 256;
    int eb  = (E + 255) / 256;
    int gb  = (n + 15) / 16;
    int ab  = (n * 16 + 255) / 256;
    int nb1 = (n + SCAN_B - 1) / SCAN_B;

    // ---- CSR build (int atomics only) ----
    k_zero_deg  <<<nb, 256>>>(n);
    k_count     <<<eb, 256>>>(ei, E);
    k_dinv      <<<nb, 256>>>(n);
    k_scan_local<<<nb1, SCAN_B>>>(n);
    k_scan_bsums<<<1, 128>>>(nb1);
    k_scan_add  <<<nb1, SCAN_B>>>(n, E);
    k_place     <<<eb, 256>>>(ei, E);

    // ---- layer 1 ----
    k_gemm<false>     <<<gb, 256>>>(x, W1, b1, n);
    k_aggregate<false><<<ab, 256>>>(b1, out, n);

    // ---- layer 2 (bias+relu of layer 1 fused into GEMM input load;
    //      bias+relu of layer 2 fused into aggregate epilogue) ----
    k_gemm<true>      <<<gb, 256>>>(x /*unused*/, W2, b1, n);
    k_aggregate<true> <<<ab, 256>>>(b2, out, n);
}

// round 6
// speedup vs baseline: 1.6288x; 1.5221x over previous
#include <cuda_runtime.h>
#include <stdint.h>

#define NMAX 100000
#define EMAX 1600000
#define F    64
#define F4   16          // float4 per node row
#define GR   64          // gemm rows per block
#define SCAN_B 1024
#define NB1MAX ((NMAX + SCAN_B - 1) / SCAN_B)   // 98

// ---- scratch (device globals: allocation-free) ----
__device__ int    g_degi[NMAX];
__device__ float  g_dinv[NMAX];
__device__ int    g_off [NMAX + 1];
__device__ int    g_cur [NMAX];
__device__ int    g_bsum[NB1MAX + 1];
__device__ int    g_es  [EMAX];                // edge records: src only
__device__ float4 g_h   [(size_t)NMAX * F4];   // layer h (raw in L1, pre-scaled in L2)
__device__ float4 g_agg [(size_t)NMAX * F4];   // layer-1 aggregate (pre bias/relu)

// ---------------------------------------------------------------------------
__global__ void k_zero_deg(int n) {
    int i = blockIdx.x * blockDim.x + threadIdx.x;
    if (i < n) g_degi[i] = 0;
}

__global__ void k_count(const int* __restrict__ ei, int E) {
    int e = blockIdx.x * blockDim.x + threadIdx.x;
    if (e < E) atomicAdd(&g_degi[ei[e + E]], 1);
}

// ---- exclusive scan over degrees (dinv fused into stage 1) ----
__global__ void k_scan_local(int n) {
    __shared__ int wsum[32];
    int i = blockIdx.x * SCAN_B + threadIdx.x;
    int lane = threadIdx.x & 31, wid = threadIdx.x >> 5;
    int v = (i < n) ? g_degi[i] : 0;
    if (i < n) g_dinv[i] = rsqrtf((float)v + 1.0f);   // + self loop
    int s = v;
#pragma unroll
    for (int o = 1; o < 32; o <<= 1) {
        int u = __shfl_up_sync(0xffffffffu, s, o);
        if (lane >= o) s += u;
    }
    if (lane == 31) wsum[wid] = s;
    __syncthreads();
    if (wid == 0) {
        int ws = wsum[lane];
#pragma unroll
        for (int o = 1; o < 32; o <<= 1) {
            int u = __shfl_up_sync(0xffffffffu, ws, o);
            if (lane >= o) ws += u;
        }
        wsum[lane] = ws;
    }
    __syncthreads();
    int excl = s - v + (wid > 0 ? wsum[wid - 1] : 0);
    if (i < n) g_off[i] = excl;
    if (threadIdx.x == 0) g_bsum[blockIdx.x] = wsum[31];
}

__global__ void k_scan_bsums(int nb) {   // single block, 128 threads
    __shared__ int wsum[4];
    int t = threadIdx.x;
    int lane = t & 31, wid = t >> 5;
    int v = (t < nb) ? g_bsum[t] : 0;
    int s = v;
#pragma unroll
    for (int o = 1; o < 32; o <<= 1) {
        int u = __shfl_up_sync(0xffffffffu, s, o);
        if (lane >= o) s += u;
    }
    if (lane == 31) wsum[wid] = s;
    __syncthreads();
    int base = 0;
    for (int w = 0; w < wid; w++) base += wsum[w];
    if (t < nb) g_bsum[t] = s - v + base;
}

__global__ void k_scan_add(int n, int E) {
    int i = blockIdx.x * SCAN_B + threadIdx.x;
    if (i < n) {
        int o = g_off[i] + g_bsum[blockIdx.x];
        g_off[i] = o;
        g_cur[i] = o;
    }
    if (i == 0) g_off[n] = E;
}

__global__ void k_place(const int* __restrict__ ei, int E) {
    int e = blockIdx.x * blockDim.x + threadIdx.x;
    if (e < E) {
        int s = ei[e];
        int d = ei[e + E];
        int pos = atomicAdd(&g_cur[d], 1);
        g_es[pos] = s;
    }
}

// ---------------------------------------------------------------------------
// GEMM: 64 rows/block, 256 threads; thread computes 4 rows x 4 cols.
// RELU_BIAS: input v -> relu(v + bias) (layer 2 reads g_agg).
// PRESCALE:  epilogue multiplies by dinv[row] (layer 2 only; layer-1 GEMM
//            runs concurrently with the CSR build so dinv is not ready).
template <bool RELU_BIAS, bool PRESCALE>
__global__ void k_gemm(const float* in, const float* __restrict__ W,
                       const float* __restrict__ bias, int n)
{
    __shared__ float Ws[F * F];
    __shared__ float xs[GR * F];

    int tid = threadIdx.x;
    int tx = tid & 15;
    int ty = tid >> 4;
    int r0 = blockIdx.x * GR;

    {   // W: 1024 float4s
        const float4* W4 = reinterpret_cast<const float4*>(W);
        float4* Ws4 = reinterpret_cast<float4*>(Ws);
        for (int i = tid; i < F * F4; i += 256) Ws4[i] = __ldg(&W4[i]);
    }
    {   // input tile: 1024 float4s
        float4* xs4 = reinterpret_cast<float4*>(xs);
        for (int i = tid; i < GR * F4; i += 256) {
            int row = i >> 4;
            int c4  = i & 15;
            int gr  = r0 + row;
            float4 v = make_float4(0.f, 0.f, 0.f, 0.f);
            if (RELU_BIAS) {
                if (gr < n) v = g_agg[(size_t)gr * F4 + c4];
                float4 bb = __ldg(&reinterpret_cast<const float4*>(bias)[c4]);
                v.x = fmaxf(v.x + bb.x, 0.f);
                v.y = fmaxf(v.y + bb.y, 0.f);
                v.z = fmaxf(v.z + bb.z, 0.f);
                v.w = fmaxf(v.w + bb.w, 0.f);
            } else {
                if (gr < n)
                    v = __ldg(&reinterpret_cast<const float4*>(in)[(size_t)gr * F4 + c4]);
            }
            xs4[i] = v;
        }
    }
    __syncthreads();

    float4 acc[4];
#pragma unroll
    for (int rr = 0; rr < 4; rr++) acc[rr] = make_float4(0.f, 0.f, 0.f, 0.f);

#pragma unroll
    for (int k = 0; k < F; k++) {
        float4 w = *reinterpret_cast<const float4*>(&Ws[k * F + tx * 4]);
#pragma unroll
        for (int rr = 0; rr < 4; rr++) {
            float xv = xs[(ty + 16 * rr) * F + k];
            acc[rr].x = fmaf(xv, w.x, acc[rr].x);
            acc[rr].y = fmaf(xv, w.y, acc[rr].y);
            acc[rr].z = fmaf(xv, w.z, acc[rr].z);
            acc[rr].w = fmaf(xv, w.w, acc[rr].w);
        }
    }

#pragma unroll
    for (int rr = 0; rr < 4; rr++) {
        int row = r0 + ty + 16 * rr;
        if (row < n) {
            float sc = PRESCALE ? g_dinv[row] : 1.0f;
            g_h[(size_t)row * F4 + tx] =
                make_float4(acc[rr].x * sc, acc[rr].y * sc, acc[rr].z * sc, acc[rr].w * sc);
        }
    }
}

// ---------------------------------------------------------------------------
// Aggregate: 16 lanes/node (lane owns a float4 slice). Each lane loads ONE
// edge index (+ dinv[src] weight when !PRESCALED) per 16-edge chunk; values
// distributed by width-16 shuffles. Register accumulation, one store/node.
// FINAL=false: g_agg = acc*dinv (layer 1). FINAL=true: out = relu(acc*dinv+b).
template <bool PRESCALED, bool FINAL>
__global__ void k_aggregate(const float* __restrict__ bias, float* __restrict__ out, int n)
{
    int t = blockIdx.x * blockDim.x + threadIdx.x;
    int node = t >> 4;
    if (node >= n) return;
    int lane = threadIdx.x & 15;
    unsigned gmask = 0xFFFFu << (threadIdx.x & 16);

    int beg = g_off[node];
    int end = g_off[node + 1];
    float di = g_dinv[node];

    size_t idx = (size_t)node * F4 + lane;
    float4 acc = g_h[idx];                    // self-loop term
    if (!PRESCALED) {                         // raw h: weight self by dinv[node]
        acc.x *= di; acc.y *= di; acc.z *= di; acc.w *= di;
    }

    for (int base = beg; base < end; base += 16) {
        int p = base + lane;
        int   s_my = 0;
        float w_my = 0.f;
        if (p < end) {
            s_my = __ldg(&g_es[p]);
            if (!PRESCALED) w_my = __ldg(&g_dinv[s_my]);
        }
        int cnt = end - base; if (cnt > 16) cnt = 16;

        int j = 0;
        for (; j + 4 <= cnt; j += 4) {
            int s0 = __shfl_sync(gmask, s_my, j + 0, 16);
            int s1 = __shfl_sync(gmask, s_my, j + 1, 16);
            int s2 = __shfl_sync(gmask, s_my, j + 2, 16);
            int s3 = __shfl_sync(gmask, s_my, j + 3, 16);
            float4 v0 = __ldg(&g_h[(size_t)s0 * F4 + lane]);
            float4 v1 = __ldg(&g_h[(size_t)s1 * F4 + lane]);
            float4 v2 = __ldg(&g_h[(size_t)s2 * F4 + lane]);
            float4 v3 = __ldg(&g_h[(size_t)s3 * F4 + lane]);
            if (PRESCALED) {
                acc.x += v0.x + v1.x + v2.x + v3.x;
                acc.y += v0.y + v1.y + v2.y + v3.y;
                acc.z += v0.z + v1.z + v2.z + v3.z;
                acc.w += v0.w + v1.w + v2.w + v3.w;
            } else {
                float w0 = __shfl_sync(gmask, w_my, j + 0, 16);
                float w1 = __shfl_sync(gmask, w_my, j + 1, 16);
                float w2 = __shfl_sync(gmask, w_my, j + 2, 16);
                float w3 = __shfl_sync(gmask, w_my, j + 3, 16);
                acc.x = fmaf(v0.x, w0, acc.x); acc.y = fmaf(v0.y, w0, acc.y);
                acc.z = fmaf(v0.z, w0, acc.z); acc.w = fmaf(v0.w, w0, acc.w);
                acc.x = fmaf(v1.x, w1, acc.x); acc.y = fmaf(v1.y, w1, acc.y);
                acc.z = fmaf(v1.z, w1, acc.z); acc.w = fmaf(v1.w, w1, acc.w);
                acc.x = fmaf(v2.x, w2, acc.x); acc.y = fmaf(v2.y, w2, acc.y);
                acc.z = fmaf(v2.z, w2, acc.z); acc.w = fmaf(v2.w, w2, acc.w);
                acc.x = fmaf(v3.x, w3, acc.x); acc.y = fmaf(v3.y, w3, acc.y);
                acc.z = fmaf(v3.z, w3, acc.z); acc.w = fmaf(v3.w, w3, acc.w);
            }
        }
        for (; j < cnt; j++) {
            int s0 = __shfl_sync(gmask, s_my, j, 16);
            float4 v0 = __ldg(&g_h[(size_t)s0 * F4 + lane]);
            if (PRESCALED) {
                acc.x += v0.x; acc.y += v0.y; acc.z += v0.z; acc.w += v0.w;
            } else {
                float w0 = __shfl_sync(gmask, w_my, j, 16);
                acc.x = fmaf(v0.x, w0, acc.x); acc.y = fmaf(v0.y, w0, acc.y);
                acc.z = fmaf(v0.z, w0, acc.z); acc.w = fmaf(v0.w, w0, acc.w);
            }
        }
    }

    if (FINAL) {
        float4 bb = __ldg(&reinterpret_cast<const float4*>(bias)[lane]);
        float4 o;
        o.x = fmaxf(fmaf(acc.x, di, bb.x), 0.f);
        o.y = fmaxf(fmaf(acc.y, di, bb.y), 0.f);
        o.z = fmaxf(fmaf(acc.z, di, bb.z), 0.f);
        o.w = fmaxf(fmaf(acc.w, di, bb.w), 0.f);
        reinterpret_cast<float4*>(out)[idx] = o;
    } else {
        g_agg[idx] = make_float4(acc.x * di, acc.y * di, acc.z * di, acc.w * di);
    }
}

// ---------------------------------------------------------------------------
extern "C" void kernel_launch(void* const* d_in, const int* in_sizes, int n_in,
                              void* d_out, int out_size)
{
    const float* x  = (const float*)d_in[0];
    const int*   ei = (const int*)d_in[1];     // int32 (JAX default x64-off)
    const float* W1 = (const float*)d_in[2];
    const float* b1 = (const float*)d_in[3];
    const float* W2 = (const float*)d_in[4];
    const float* b2 = (const float*)d_in[5];
    float*       out = (float*)d_out;

    int n = in_sizes[0] / F;       // 100000
    int E = in_sizes[1] / 2;       // 1600000
    if (n > NMAX) n = NMAX;
    if (E > EMAX) E = EMAX;

    int nb  = (n + 255) / 256;
    int eb  = (E + 255) / 256;
    int gb  = (n + GR - 1) / GR;
    int ab  = (n * 16 + 255) / 256;
    int nb1 = (n + SCAN_B - 1) / SCAN_B;

    // one-time side stream + events (not device memory; deterministic)
    static cudaStream_t s_side = nullptr;
    static cudaEvent_t  e_fork = nullptr, e_join = nullptr;
    if (!s_side) {
        cudaStreamCreateWithFlags(&s_side, cudaStreamNonBlocking);
        cudaEventCreateWithFlags(&e_fork, cudaEventDisableTiming);
        cudaEventCreateWithFlags(&e_join, cudaEventDisableTiming);
    }

    // ---- fork: layer-1 GEMM (independent of CSR build) on side stream ----
    cudaEventRecord(e_fork, 0);
    cudaStreamWaitEvent(s_side, e_fork, 0);
    k_gemm<false, false><<<gb, 256, 0, s_side>>>(x, W1, b1, n);
    cudaEventRecord(e_join, s_side);

    // ---- CSR build on main stream ----
    k_zero_deg  <<<nb, 256>>>(n);
    k_count     <<<eb, 256>>>(ei, E);
    k_scan_local<<<nb1, SCAN_B>>>(n);          // also computes dinv
    k_scan_bsums<<<1, 128>>>(nb1);
    k_scan_add  <<<nb1, SCAN_B>>>(n, E);
    k_place     <<<eb, 256>>>(ei, E);

    // ---- join, then layer-1 aggregate ----
    cudaStreamWaitEvent(0, e_join, 0);
    k_aggregate<false, false><<<ab, 256>>>(b1, out, n);

    // ---- layer 2 ----
    k_gemm<true, true>  <<<gb, 256>>>(x /*unused*/, W2, b1, n);
    k_aggregate<true, true><<<ab, 256>>>(b2, out, n);
}

// round 7
// speedup vs baseline: 1.7929x; 1.1008x over previous
#include <cuda_runtime.h>
#include <cuda_fp16.h>
#include <stdint.h>

#define NMAX 100000
#define EMAX 1600000
#define F    64
#define F4   16          // float4 per node row
#define GR   64          // gemm rows per block
#define SCAN_B 1024
#define NB1MAX ((NMAX + SCAN_B - 1) / SCAN_B)   // 98

// ---- scratch (device globals: allocation-free) ----
__device__ int    g_degi[NMAX];
__device__ float  g_dinv[NMAX];
__device__ int    g_off [NMAX + 1];
__device__ int    g_cur [NMAX];
__device__ int    g_bsum[NB1MAX + 1];
__device__ int    g_es  [EMAX];                // edge records: src only
__device__ uint4  g_hh  [(size_t)NMAX * 8];    // h in fp16 (8 uint4 = 64 halves/row)
__device__ float4 g_agg [(size_t)NMAX * F4];   // layer-1 aggregate (fp32)

// ---------------------------------------------------------------------------
__global__ void k_zero_deg(int n) {
    int i = blockIdx.x * blockDim.x + threadIdx.x;
    if (i < n) g_degi[i] = 0;
}

__global__ void k_count(const int* __restrict__ ei, int E) {
    int e = blockIdx.x * blockDim.x + threadIdx.x;
    if (e < E) atomicAdd(&g_degi[ei[e + E]], 1);
}

// ---- exclusive scan over degrees (dinv fused into stage 1) ----
__global__ void k_scan_local(int n) {
    __shared__ int wsum[32];
    int i = blockIdx.x * SCAN_B + threadIdx.x;
    int lane = threadIdx.x & 31, wid = threadIdx.x >> 5;
    int v = (i < n) ? g_degi[i] : 0;
    if (i < n) g_dinv[i] = rsqrtf((float)v + 1.0f);   // + self loop
    int s = v;
#pragma unroll
    for (int o = 1; o < 32; o <<= 1) {
        int u = __shfl_up_sync(0xffffffffu, s, o);
        if (lane >= o) s += u;
    }
    if (lane == 31) wsum[wid] = s;
    __syncthreads();
    if (wid == 0) {
        int ws = wsum[lane];
#pragma unroll
        for (int o = 1; o < 32; o <<= 1) {
            int u = __shfl_up_sync(0xffffffffu, ws, o);
            if (lane >= o) ws += u;
        }
        wsum[lane] = ws;
    }
    __syncthreads();
    int excl = s - v + (wid > 0 ? wsum[wid - 1] : 0);
    if (i < n) g_off[i] = excl;
    if (threadIdx.x == 0) g_bsum[blockIdx.x] = wsum[31];
}

__global__ void k_scan_bsums(int nb) {   // single block, 128 threads
    __shared__ int wsum[4];
    int t = threadIdx.x;
    int lane = t & 31, wid = t >> 5;
    int v = (t < nb) ? g_bsum[t] : 0;
    int s = v;
#pragma unroll
    for (int o = 1; o < 32; o <<= 1) {
        int u = __shfl_up_sync(0xffffffffu, s, o);
        if (lane >= o) s += u;
    }
    if (lane == 31) wsum[wid] = s;
    __syncthreads();
    int base = 0;
    for (int w = 0; w < wid; w++) base += wsum[w];
    if (t < nb) g_bsum[t] = s - v + base;
}

__global__ void k_scan_add(int n, int E) {
    int i = blockIdx.x * SCAN_B + threadIdx.x;
    if (i < n) {
        int o = g_off[i] + g_bsum[blockIdx.x];
        g_off[i] = o;
        g_cur[i] = o;
    }
    if (i == 0) g_off[n] = E;
}

__global__ void k_place(const int* __restrict__ ei, int E) {
    int e = blockIdx.x * blockDim.x + threadIdx.x;
    if (e < E) {
        int s = ei[e];
        int d = ei[e + E];
        int pos = atomicAdd(&g_cur[d], 1);
        g_es[pos] = s;
    }
}

// ---------------------------------------------------------------------------
// GEMM: 64 rows/block, 256 threads; thread computes 4 rows x 4 cols.
// Epilogue packs to fp16 (g_hh). PRESCALE multiplies by dinv[row] (layer 2).
template <bool RELU_BIAS, bool PRESCALE>
__global__ void k_gemm(const float* in, const float* __restrict__ W,
                       const float* __restrict__ bias, int n)
{
    __shared__ float Ws[F * F];
    __shared__ float xs[GR * F];

    int tid = threadIdx.x;
    int tx = tid & 15;
    int ty = tid >> 4;
    int r0 = blockIdx.x * GR;

    {   // W: 1024 float4s
        const float4* W4 = reinterpret_cast<const float4*>(W);
        float4* Ws4 = reinterpret_cast<float4*>(Ws);
        for (int i = tid; i < F * F4; i += 256) Ws4[i] = __ldg(&W4[i]);
    }
    {   // input tile: 1024 float4s
        float4* xs4 = reinterpret_cast<float4*>(xs);
        for (int i = tid; i < GR * F4; i += 256) {
            int row = i >> 4;
            int c4  = i & 15;
            int gr  = r0 + row;
            float4 v = make_float4(0.f, 0.f, 0.f, 0.f);
            if (RELU_BIAS) {
                if (gr < n) v = g_agg[(size_t)gr * F4 + c4];
                float4 bb = __ldg(&reinterpret_cast<const float4*>(bias)[c4]);
                v.x = fmaxf(v.x + bb.x, 0.f);
                v.y = fmaxf(v.y + bb.y, 0.f);
                v.z = fmaxf(v.z + bb.z, 0.f);
                v.w = fmaxf(v.w + bb.w, 0.f);
            } else {
                if (gr < n)
                    v = __ldg(&reinterpret_cast<const float4*>(in)[(size_t)gr * F4 + c4]);
            }
            xs4[i] = v;
        }
    }
    __syncthreads();

    float4 acc[4];
#pragma unroll
    for (int rr = 0; rr < 4; rr++) acc[rr] = make_float4(0.f, 0.f, 0.f, 0.f);

#pragma unroll
    for (int k = 0; k < F; k++) {
        float4 w = *reinterpret_cast<const float4*>(&Ws[k * F + tx * 4]);
#pragma unroll
        for (int rr = 0; rr < 4; rr++) {
            float xv = xs[(ty + 16 * rr) * F + k];
            acc[rr].x = fmaf(xv, w.x, acc[rr].x);
            acc[rr].y = fmaf(xv, w.y, acc[rr].y);
            acc[rr].z = fmaf(xv, w.z, acc[rr].z);
            acc[rr].w = fmaf(xv, w.w, acc[rr].w);
        }
    }

#pragma unroll
    for (int rr = 0; rr < 4; rr++) {
        int row = r0 + ty + 16 * rr;
        if (row < n) {
            float sc = PRESCALE ? g_dinv[row] : 1.0f;
            __half2 h01 = __floats2half2_rn(acc[rr].x * sc, acc[rr].y * sc);
            __half2 h23 = __floats2half2_rn(acc[rr].z * sc, acc[rr].w * sc);
            uint2 u;
            u.x = reinterpret_cast<unsigned&>(h01);
            u.y = reinterpret_cast<unsigned&>(h23);
            reinterpret_cast<uint2*>(g_hh)[(size_t)row * 16 + tx] = u;
        }
    }
}

// ---------------------------------------------------------------------------
// Aggregate: 8 lanes/node; lane owns 8 features (one uint4 = 8 fp16).
// One index (+weight) load per lane per 8-edge chunk; width-8 shuffles.
// fp32 accumulation; one non-atomic store per node.
template <bool PRESCALED, bool FINAL>
__global__ void k_aggregate(const float* __restrict__ bias, float* __restrict__ out, int n)
{
    int t = blockIdx.x * blockDim.x + threadIdx.x;
    int node = t >> 3;
    if (node >= n) return;
    int lane = threadIdx.x & 7;
    unsigned gmask = 0xFFu << (threadIdx.x & 24);

    int beg = g_off[node];
    int end = g_off[node + 1];
    float di = g_dinv[node];

    // self-loop term
    float acc[8];
    {
        uint4 u = g_hh[(size_t)node * 8 + lane];
        float sw = PRESCALED ? 1.0f : di;
        float2 f0 = __half22float2(reinterpret_cast<__half2&>(u.x));
        float2 f1 = __half22float2(reinterpret_cast<__half2&>(u.y));
        float2 f2 = __half22float2(reinterpret_cast<__half2&>(u.z));
        float2 f3 = __half22float2(reinterpret_cast<__half2&>(u.w));
        acc[0] = f0.x * sw; acc[1] = f0.y * sw;
        acc[2] = f1.x * sw; acc[3] = f1.y * sw;
        acc[4] = f2.x * sw; acc[5] = f2.y * sw;
        acc[6] = f3.x * sw; acc[7] = f3.y * sw;
    }

    for (int base = beg; base < end; base += 8) {
        int p = base + lane;
        int   s_my = 0;
        float w_my = 1.0f;
        if (p < end) {
            s_my = __ldg(&g_es[p]);
            if (!PRESCALED) w_my = __ldg(&g_dinv[s_my]);
        }
        int cnt = end - base; if (cnt > 8) cnt = 8;

#pragma unroll 4
        for (int j = 0; j < cnt; j++) {
            int s0 = __shfl_sync(gmask, s_my, j, 8);
            uint4 u = __ldg(&g_hh[(size_t)s0 * 8 + lane]);
            float2 f0 = __half22float2(reinterpret_cast<__half2&>(u.x));
            float2 f1 = __half22float2(reinterpret_cast<__half2&>(u.y));
            float2 f2 = __half22float2(reinterpret_cast<__half2&>(u.z));
            float2 f3 = __half22float2(reinterpret_cast<__half2&>(u.w));
            if (PRESCALED) {
                acc[0] += f0.x; acc[1] += f0.y;
                acc[2] += f1.x; acc[3] += f1.y;
                acc[4] += f2.x; acc[5] += f2.y;
                acc[6] += f3.x; acc[7] += f3.y;
            } else {
                float w0 = __shfl_sync(gmask, w_my, j, 8);
                acc[0] = fmaf(f0.x, w0, acc[0]); acc[1] = fmaf(f0.y, w0, acc[1]);
                acc[2] = fmaf(f1.x, w0, acc[2]); acc[3] = fmaf(f1.y, w0, acc[3]);
                acc[4] = fmaf(f2.x, w0, acc[4]); acc[5] = fmaf(f2.y, w0, acc[5]);
                acc[6] = fmaf(f3.x, w0, acc[6]); acc[7] = fmaf(f3.y, w0, acc[7]);
            }
        }
    }

    size_t oidx = (size_t)node * F4 + lane * 2;
    if (FINAL) {
        float4 b0 = __ldg(&reinterpret_cast<const float4*>(bias)[lane * 2]);
        float4 b1 = __ldg(&reinterpret_cast<const float4*>(bias)[lane * 2 + 1]);
        float4 o0, o1;
        o0.x = fmaxf(fmaf(acc[0], di, b0.x), 0.f);
        o0.y = fmaxf(fmaf(acc[1], di, b0.y), 0.f);
        o0.z = fmaxf(fmaf(acc[2], di, b0.z), 0.f);
        o0.w = fmaxf(fmaf(acc[3], di, b0.w), 0.f);
        o1.x = fmaxf(fmaf(acc[4], di, b1.x), 0.f);
        o1.y = fmaxf(fmaf(acc[5], di, b1.y), 0.f);
        o1.z = fmaxf(fmaf(acc[6], di, b1.z), 0.f);
        o1.w = fmaxf(fmaf(acc[7], di, b1.w), 0.f);
        reinterpret_cast<float4*>(out)[oidx]     = o0;
        reinterpret_cast<float4*>(out)[oidx + 1] = o1;
    } else {
        g_agg[oidx] = make_float4(acc[0] * di, acc[1] * di, acc[2] * di, acc[3] * di);
        g_agg[oidx + 1] = make_float4(acc[4] * di, acc[5] * di, acc[6] * di, acc[7] * di);
    }
}

// ---------------------------------------------------------------------------
extern "C" void kernel_launch(void* const* d_in, const int* in_sizes, int n_in,
                              void* d_out, int out_size)
{
    const float* x  = (const float*)d_in[0];
    const int*   ei = (const int*)d_in[1];     // int32 (JAX default x64-off)
    const float* W1 = (const float*)d_in[2];
    const float* b1 = (const float*)d_in[3];
    const float* W2 = (const float*)d_in[4];
    const float* b2 = (const float*)d_in[5];
    float*       out = (float*)d_out;

    int n = in_sizes[0] / F;       // 100000
    int E = in_sizes[1] / 2;       // 1600000
    if (n > NMAX) n = NMAX;
    if (E > EMAX) E = EMAX;

    int nb  = (n + 255) / 256;
    int eb  = (E + 255) / 256;
    int gb  = (n + GR - 1) / GR;
    int ab  = (n * 8 + 255) / 256;
    int nb1 = (n + SCAN_B - 1) / SCAN_B;

    // one-time side stream + events (not device memory; deterministic)
    static cudaStream_t s_side = nullptr;
    static cudaEvent_t  e_fork = nullptr, e_join = nullptr;
    if (!s_side) {
        cudaStreamCreateWithFlags(&s_side, cudaStreamNonBlocking);
        cudaEventCreateWithFlags(&e_fork, cudaEventDisableTiming);
        cudaEventCreateWithFlags(&e_join, cudaEventDisableTiming);
    }

    // ---- fork: layer-1 GEMM (independent of CSR build) on side stream ----
    cudaEventRecord(e_fork, 0);
    cudaStreamWaitEvent(s_side, e_fork, 0);
    k_gemm<false, false><<<gb, 256, 0, s_side>>>(x, W1, b1, n);
    cudaEventRecord(e_join, s_side);

    // ---- CSR build on main stream ----
    k_zero_deg  <<<nb, 256>>>(n);
    k_count     <<<eb, 256>>>(ei, E);
    k_scan_local<<<nb1, SCAN_B>>>(n);          // also computes dinv
    k_scan_bsums<<<1, 128>>>(nb1);
    k_scan_add  <<<nb1, SCAN_B>>>(n, E);
    k_place     <<<eb, 256>>>(ei, E);

    // ---- join, then layer-1 aggregate ----
    cudaStreamWaitEvent(0, e_join, 0);
    k_aggregate<false, false><<<ab, 256>>>(b1, out, n);

    // ---- layer 2 ----
    k_gemm<true, true>     <<<gb, 256>>>(x /*unused*/, W2, b1, n);
    k_aggregate<true, true><<<ab, 256>>>(b2, out, n);
}